// round 4
// baseline (speedup 1.0000x reference)
#include <cuda_runtime.h>
#include <math.h>

#define H 128
#define S 64
#define PRED 50
#define BT 16
#define NBLK 128
#define NTHR 512

// ---------- gate-interleaved transposed weights: [k][j*4+g] ----------
__device__ __align__(16) float g_wx0[4 * 512];      // wih0: k<4
__device__ __align__(16) float g_wh0[128 * 512];
__device__ __align__(16) float g_b0[512];           // bih0+bhh0, [j*4+g]
__device__ __align__(16) float g_wi1[128 * 512];
__device__ __align__(16) float g_wh1[128 * 512];
__device__ __align__(16) float g_b1[512];
__device__ __align__(16) float g_wgi0[128 * 512];   // GRU: gate 3 padded 0
__device__ __align__(16) float g_wgh0[128 * 512];
__device__ __align__(16) float g_wgi1[128 * 512];
__device__ __align__(16) float g_wgh1[128 * 512];
__device__ __align__(16) float g_bgi0[512];
__device__ __align__(16) float g_bgh0[512];
__device__ __align__(16) float g_bgi1[512];
__device__ __align__(16) float g_bgh1[512];
__device__ __align__(16) float g_wbr[128 * 128];    // [k][j]
__device__ __align__(16) float g_wfc1[128 * 64];    // [k][c]

__global__ void prep_kernel(
    const float* __restrict__ lwih0, const float* __restrict__ lwhh0,
    const float* __restrict__ lbih0, const float* __restrict__ lbhh0,
    const float* __restrict__ lwih1, const float* __restrict__ lwhh1,
    const float* __restrict__ lbih1, const float* __restrict__ lbhh1,
    const float* __restrict__ gwi0, const float* __restrict__ gwh0,
    const float* __restrict__ gbi0, const float* __restrict__ gbh0,
    const float* __restrict__ gwi1, const float* __restrict__ gwh1,
    const float* __restrict__ gbi1, const float* __restrict__ gbh1,
    const float* __restrict__ brw, const float* __restrict__ fc1w)
{
    int i0 = blockIdx.x * blockDim.x + threadIdx.x;
    int st = gridDim.x * blockDim.x;
    for (int i = i0; i < 4 * 512; i += st) {
        int k = i >> 9, jg = i & 511, j = jg >> 2, g = jg & 3;
        g_wx0[i] = lwih0[(g * 128 + j) * 4 + k];
    }
    for (int i = i0; i < 128 * 512; i += st) {
        int k = i >> 9, jg = i & 511, j = jg >> 2, g = jg & 3;
        int row = g * 128 + j;
        g_wh0[i] = lwhh0[row * 128 + k];
        g_wi1[i] = lwih1[row * 128 + k];
        g_wh1[i] = lwhh1[row * 128 + k];
        g_wgi0[i] = (g < 3) ? gwi0[row * 128 + k] : 0.f;
        g_wgh0[i] = (g < 3) ? gwh0[row * 128 + k] : 0.f;
        g_wgi1[i] = (g < 3) ? gwi1[row * 128 + k] : 0.f;
        g_wgh1[i] = (g < 3) ? gwh1[row * 128 + k] : 0.f;
    }
    for (int i = i0; i < 512; i += st) {
        int j = i >> 2, g = i & 3;
        int row = g * 128 + j;
        g_b0[i] = lbih0[row] + lbhh0[row];
        g_b1[i] = lbih1[row] + lbhh1[row];
        g_bgi0[i] = (g < 3) ? gbi0[row] : 0.f;
        g_bgh0[i] = (g < 3) ? gbh0[row] : 0.f;
        g_bgi1[i] = (g < 3) ? gbi1[row] : 0.f;
        g_bgh1[i] = (g < 3) ? gbh1[row] : 0.f;
    }
    for (int i = i0; i < 128 * 128; i += st) {
        int k = i >> 7, j = i & 127;
        g_wbr[i] = brw[j * 128 + k];
    }
    for (int i = i0; i < 128 * 64; i += st) {
        int k = i / 64, c = i % 64;
        g_wfc1[i] = fc1w[c * 128 + k];
    }
}

__device__ __forceinline__ float sigm(float v) { return 1.f / (1.f + __expf(-v)); }

// Pipelined: acc[q][g] += sum_k A[r0+q][k] * W[k][j*4+g].
// Weight loads run at prefetch distance 2 (~128 FMA-cycles) to cover L2 latency.
template<int NG>
__device__ __forceinline__ void mmp(const float* __restrict__ A,
                                    const float* __restrict__ W,
                                    int r0, int j4, float (&acc)[4][NG])
{
    float4 wb[3][4];
#pragma unroll
    for (int kk = 0; kk < 4; kk++) wb[0][kk] = *(const float4*)(W + kk * 512 + j4);
#pragma unroll
    for (int kk = 0; kk < 4; kk++) wb[1][kk] = *(const float4*)(W + (4 + kk) * 512 + j4);

#pragma unroll 3
    for (int kq = 0; kq < 32; kq++) {
        if (kq < 30) {
            const float* Wn = W + (kq + 2) * 4 * 512 + j4;
#pragma unroll
            for (int kk = 0; kk < 4; kk++)
                wb[(kq + 2) % 3][kk] = *(const float4*)(Wn + kk * 512);
        }
        const float4* wq = wb[kq % 3];
#pragma unroll
        for (int q = 0; q < 4; q++) {
            float4 a = *(const float4*)(A + (r0 + q) * H + kq * 4);
#pragma unroll
            for (int g = 0; g < NG; g++) {
                acc[q][g] = fmaf(a.x, (&wq[0].x)[g], acc[q][g]);
                acc[q][g] = fmaf(a.y, (&wq[1].x)[g], acc[q][g]);
                acc[q][g] = fmaf(a.z, (&wq[2].x)[g], acc[q][g]);
                acc[q][g] = fmaf(a.w, (&wq[3].x)[g], acc[q][g]);
            }
        }
    }
}

__global__ void __launch_bounds__(NTHR, 1) rnn_kernel(
    const float* __restrict__ x,
    const float* __restrict__ brb, const float* __restrict__ fc1b,
    const float* __restrict__ fc2w, const float* __restrict__ fc2b,
    float* __restrict__ out)
{
    extern __shared__ float sm[];
    float* xs  = sm;              // [16][256]
    float* h0b = xs + 4096;       // [2][16][128] ping-pong
    float* h1b = h0b + 4096;
    float* d0b = h1b + 4096;
    float* d1b = d0b + 4096;
    float* fcz = d1b + 4096;      // [16][64]

    const int tid = threadIdx.x;
    const int rg = tid >> 7;
    const int j  = tid & 127;
    const int j4 = j * 4;
    const int r0 = rg * 4;
    const int b0 = blockIdx.x * BT;

    for (int i = tid; i < BT * 256; i += NTHR) {
        int r = i >> 8, q = i & 255;
        xs[i] = x[(size_t)(b0 + r) * 256 + q];
    }
#pragma unroll
    for (int q = 0; q < 4; q++) {
        h0b[(r0 + q) * H + j] = 0.f;
        h1b[(r0 + q) * H + j] = 0.f;
    }
    float c0r[4] = {0.f, 0.f, 0.f, 0.f};
    float c1r[4] = {0.f, 0.f, 0.f, 0.f};
    __syncthreads();

    // ---------------- LSTM encoder ----------------
    for (int t = 0; t < S; t++) {
        const int p = t & 1, np = p ^ 1;
        const float* h0p = h0b + p * 2048;
        float*       h0n = h0b + np * 2048;
        const float* h1p = h1b + p * 2048;
        float*       h1n = h1b + np * 2048;

        // layer 0
        {
            float acc[4][4];
            float4 bb = *(const float4*)(g_b0 + j4);
#pragma unroll
            for (int q = 0; q < 4; q++) {
                acc[q][0] = bb.x; acc[q][1] = bb.y; acc[q][2] = bb.z; acc[q][3] = bb.w;
            }
            float4 w0 = *(const float4*)(g_wx0 + 0 * 512 + j4);
            float4 w1 = *(const float4*)(g_wx0 + 1 * 512 + j4);
            float4 w2 = *(const float4*)(g_wx0 + 2 * 512 + j4);
            float4 w3 = *(const float4*)(g_wx0 + 3 * 512 + j4);
#pragma unroll
            for (int q = 0; q < 4; q++) {
                float4 a = *(const float4*)(xs + (r0 + q) * 256 + t * 4);
                acc[q][0] = fmaf(a.x, w0.x, acc[q][0]); acc[q][1] = fmaf(a.x, w0.y, acc[q][1]);
                acc[q][2] = fmaf(a.x, w0.z, acc[q][2]); acc[q][3] = fmaf(a.x, w0.w, acc[q][3]);
                acc[q][0] = fmaf(a.y, w1.x, acc[q][0]); acc[q][1] = fmaf(a.y, w1.y, acc[q][1]);
                acc[q][2] = fmaf(a.y, w1.z, acc[q][2]); acc[q][3] = fmaf(a.y, w1.w, acc[q][3]);
                acc[q][0] = fmaf(a.z, w2.x, acc[q][0]); acc[q][1] = fmaf(a.z, w2.y, acc[q][1]);
                acc[q][2] = fmaf(a.z, w2.z, acc[q][2]); acc[q][3] = fmaf(a.z, w2.w, acc[q][3]);
                acc[q][0] = fmaf(a.w, w3.x, acc[q][0]); acc[q][1] = fmaf(a.w, w3.y, acc[q][1]);
                acc[q][2] = fmaf(a.w, w3.z, acc[q][2]); acc[q][3] = fmaf(a.w, w3.w, acc[q][3]);
            }
            mmp<4>(h0p, g_wh0, r0, j4, acc);
#pragma unroll
            for (int q = 0; q < 4; q++) {
                float cc = sigm(acc[q][1]) * c0r[q] + sigm(acc[q][0]) * tanhf(acc[q][2]);
                c0r[q] = cc;
                h0n[(r0 + q) * H + j] = sigm(acc[q][3]) * tanhf(cc);
            }
        }
        __syncthreads();

        // layer 1
        {
            float acc[4][4];
            float4 bb = *(const float4*)(g_b1 + j4);
#pragma unroll
            for (int q = 0; q < 4; q++) {
                acc[q][0] = bb.x; acc[q][1] = bb.y; acc[q][2] = bb.z; acc[q][3] = bb.w;
            }
            mmp<4>(h0n, g_wi1, r0, j4, acc);
            mmp<4>(h1p, g_wh1, r0, j4, acc);
#pragma unroll
            for (int q = 0; q < 4; q++) {
                float cc = sigm(acc[q][1]) * c1r[q] + sigm(acc[q][0]) * tanhf(acc[q][2]);
                c1r[q] = cc;
                h1n[(r0 + q) * H + j] = sigm(acc[q][3]) * tanhf(cc);
            }
        }
        __syncthreads();
    }
    const float* h0f = h0b;   // final states in buffer 0 after t=63
    const float* h1f = h1b;

    // ---------------- bridge ----------------
    {
        float a0[4], a1[4];
        float bv = brb[j];
#pragma unroll
        for (int q = 0; q < 4; q++) { a0[q] = bv; a1[q] = bv; }
#pragma unroll 4
        for (int k = 0; k < 128; k += 4) {
            float w0 = g_wbr[(k + 0) * 128 + j];
            float w1 = g_wbr[(k + 1) * 128 + j];
            float w2 = g_wbr[(k + 2) * 128 + j];
            float w3 = g_wbr[(k + 3) * 128 + j];
#pragma unroll
            for (int q = 0; q < 4; q++) {
                float4 u = *(const float4*)(h0f + (r0 + q) * H + k);
                float4 v = *(const float4*)(h1f + (r0 + q) * H + k);
                a0[q] = fmaf(u.x, w0, a0[q]); a0[q] = fmaf(u.y, w1, a0[q]);
                a0[q] = fmaf(u.z, w2, a0[q]); a0[q] = fmaf(u.w, w3, a0[q]);
                a1[q] = fmaf(v.x, w0, a1[q]); a1[q] = fmaf(v.y, w1, a1[q]);
                a1[q] = fmaf(v.z, w2, a1[q]); a1[q] = fmaf(v.w, w3, a1[q]);
            }
        }
#pragma unroll
        for (int q = 0; q < 4; q++) {
            d0b[(r0 + q) * H + j] = tanhf(a0[q]);
            d1b[(r0 + q) * H + j] = tanhf(a1[q]);
        }
    }
    __syncthreads();

    // ---------------- autoregressive GRU decode, head folded into phases ----------------
    // Phase A(t): GRU L0 + fc1(t-1) reading d1p. Phase B(t): GRU L1 + fc2(t-1).
    for (int t = 0; t < PRED; t++) {
        const int pg = t & 1, npg = pg ^ 1;
        const float* d0p = d0b + pg * 2048;
        float*       d0n = d0b + npg * 2048;
        const float* d1p = d1b + pg * 2048;
        float*       d1n = d1b + npg * 2048;
        const float* A1 = (t == 0) ? h1f : d1p;

        // --- phase A: GRU layer 0 (+ fc1 of previous step) ---
        {
            float ai[4][3], ah[4][3];
            float4 bi = *(const float4*)(g_bgi0 + j4);
            float4 bh = *(const float4*)(g_bgh0 + j4);
#pragma unroll
            for (int q = 0; q < 4; q++) {
                ai[q][0] = bi.x; ai[q][1] = bi.y; ai[q][2] = bi.z;
                ah[q][0] = bh.x; ah[q][1] = bh.y; ah[q][2] = bh.z;
            }
            mmp<3>(A1, g_wgi0, r0, j4, ai);
            mmp<3>(d0p, g_wgh0, r0, j4, ah);
#pragma unroll
            for (int q = 0; q < 4; q++) {
                float hold = d0p[(r0 + q) * H + j];
                float rr = sigm(ai[q][0] + ah[q][0]);
                float zz = sigm(ai[q][1] + ah[q][1]);
                float nn = tanhf(ai[q][2] + rr * ah[q][2]);
                d0n[(r0 + q) * H + j] = (1.f - zz) * nn + zz * hold;
            }
        }
        if (t > 0) {
            // fc1 for step t-1: input d1p (= d1n of t-1), output fcz
#pragma unroll
            for (int half = 0; half < 2; half++) {
                int o = tid + half * NTHR;
                int r = o >> 6, c = o & 63;
                float acc = fc1b[c];
#pragma unroll 4
                for (int k = 0; k < 128; k += 4) {
                    float4 hv = *(const float4*)(d1p + r * H + k);
                    acc = fmaf(hv.x, g_wfc1[(k + 0) * 64 + c], acc);
                    acc = fmaf(hv.y, g_wfc1[(k + 1) * 64 + c], acc);
                    acc = fmaf(hv.z, g_wfc1[(k + 2) * 64 + c], acc);
                    acc = fmaf(hv.w, g_wfc1[(k + 3) * 64 + c], acc);
                }
                fcz[r * 64 + c] = fmaxf(acc, 0.f);
            }
        }
        __syncthreads();

        // --- phase B: GRU layer 1 (+ fc2 of previous step) ---
        {
            float ai[4][3], ah[4][3];
            float4 bi = *(const float4*)(g_bgi1 + j4);
            float4 bh = *(const float4*)(g_bgh1 + j4);
#pragma unroll
            for (int q = 0; q < 4; q++) {
                ai[q][0] = bi.x; ai[q][1] = bi.y; ai[q][2] = bi.z;
                ah[q][0] = bh.x; ah[q][1] = bh.y; ah[q][2] = bh.z;
            }
            mmp<3>(d0n, g_wgi1, r0, j4, ai);
            mmp<3>(d1p, g_wgh1, r0, j4, ah);
#pragma unroll
            for (int q = 0; q < 4; q++) {
                float hold = d1p[(r0 + q) * H + j];
                float rr = sigm(ai[q][0] + ah[q][0]);
                float zz = sigm(ai[q][1] + ah[q][1]);
                float nn = tanhf(ai[q][2] + rr * ah[q][2]);
                d1n[(r0 + q) * H + j] = (1.f - zz) * nn + zz * hold;
            }
        }
        if (t > 0 && tid < 32) {
            int r = tid >> 1, cc = tid & 1;
            float s = fc2b[cc];
#pragma unroll
            for (int k = 0; k < 64; k++)
                s = fmaf(fcz[r * 64 + k], fc2w[cc * 64 + k], s);
            out[(size_t)(b0 + r) * PRED * 2 + (t - 1) * 2 + cc] = s;
        }
        __syncthreads();
    }

    // ---------------- tail: head for t = PRED-1 ----------------
    {
        const float* d1last = d1b;   // parity: written at t=49 into buffer 0
#pragma unroll
        for (int half = 0; half < 2; half++) {
            int o = tid + half * NTHR;
            int r = o >> 6, c = o & 63;
            float acc = fc1b[c];
#pragma unroll 4
            for (int k = 0; k < 128; k += 4) {
                float4 hv = *(const float4*)(d1last + r * H + k);
                acc = fmaf(hv.x, g_wfc1[(k + 0) * 64 + c], acc);
                acc = fmaf(hv.y, g_wfc1[(k + 1) * 64 + c], acc);
                acc = fmaf(hv.z, g_wfc1[(k + 2) * 64 + c], acc);
                acc = fmaf(hv.w, g_wfc1[(k + 3) * 64 + c], acc);
            }
            fcz[r * 64 + c] = fmaxf(acc, 0.f);
        }
        __syncthreads();
        if (tid < 32) {
            int r = tid >> 1, cc = tid & 1;
            float s = fc2b[cc];
#pragma unroll
            for (int k = 0; k < 64; k++)
                s = fmaf(fcz[r * 64 + k], fc2w[cc * 64 + k], s);
            out[(size_t)(b0 + r) * PRED * 2 + (PRED - 1) * 2 + cc] = s;
        }
    }
}

extern "C" void kernel_launch(void* const* d_in, const int* in_sizes, int n_in,
                              void* d_out, int out_size)
{
    const float* p[24];
    int np = 0;
    for (int i = 0; i < n_in && np < 24; i++) {
        if (in_sizes[i] == 1) continue;
        p[np++] = (const float*)d_in[i];
    }
    const float* x = p[0];
    const float *lwih0 = p[1], *lwhh0 = p[2], *lbih0 = p[3], *lbhh0 = p[4];
    const float *lwih1 = p[5], *lwhh1 = p[6], *lbih1 = p[7], *lbhh1 = p[8];
    const float *gwi0 = p[9], *gwh0 = p[10], *gbi0 = p[11], *gbh0 = p[12];
    const float *gwi1 = p[13], *gwh1 = p[14], *gbi1 = p[15], *gbh1 = p[16];
    const float *brw = p[17], *brb = p[18];
    const float *fc1w = p[19], *fc1b = p[20];
    const float *fc2w = p[21], *fc2b = p[22];

    prep_kernel<<<256, 256>>>(lwih0, lwhh0, lbih0, lbhh0, lwih1, lwhh1, lbih1, lbhh1,
                              gwi0, gwh0, gbi0, gbh0, gwi1, gwh1, gbi1, gbh1,
                              brw, fc1w);

    const int smem = (4096 * 5 + 1024) * (int)sizeof(float);   // 86016 B
    cudaFuncSetAttribute(rnn_kernel, cudaFuncAttributeMaxDynamicSharedMemorySize, smem);
    rnn_kernel<<<NBLK, NTHR, smem>>>(x, brb, fc1b, fc2w, fc2b, (float*)d_out);
}

// round 5
// speedup vs baseline: 1.1253x; 1.1253x over previous
#include <cuda_runtime.h>
#include <cuda_fp16.h>
#include <math.h>

#define H 128
#define S 64
#define PRED 50
#define BT 16
#define NBLK 128
#define NTHR 512

// ---------- gate-interleaved transposed weights: [k][j*4+g], fp16 for the big mats ----------
__device__ __align__(16) float  g_wx0[4 * 512];      // wih0 (tiny): fp32
__device__ __align__(16) __half g_wh0[128 * 512];
__device__ __align__(16) float  g_b0[512];           // bih0+bhh0
__device__ __align__(16) __half g_wi1[128 * 512];
__device__ __align__(16) __half g_wh1[128 * 512];
__device__ __align__(16) float  g_b1[512];
__device__ __align__(16) __half g_wgi0[128 * 512];   // GRU: gate 3 padded 0
__device__ __align__(16) __half g_wgh0[128 * 512];
__device__ __align__(16) __half g_wgi1[128 * 512];
__device__ __align__(16) __half g_wgh1[128 * 512];
__device__ __align__(16) float  g_bgi0[512];
__device__ __align__(16) float  g_bgh0[512];
__device__ __align__(16) float  g_bgi1[512];
__device__ __align__(16) float  g_bgh1[512];
__device__ __align__(16) float  g_wbr[128 * 128];    // [k][j] fp32
__device__ __align__(16) float  g_wfc1[128 * 64];    // [k][c] fp32

__global__ void prep_kernel(
    const float* __restrict__ lwih0, const float* __restrict__ lwhh0,
    const float* __restrict__ lbih0, const float* __restrict__ lbhh0,
    const float* __restrict__ lwih1, const float* __restrict__ lwhh1,
    const float* __restrict__ lbih1, const float* __restrict__ lbhh1,
    const float* __restrict__ gwi0, const float* __restrict__ gwh0,
    const float* __restrict__ gbi0, const float* __restrict__ gbh0,
    const float* __restrict__ gwi1, const float* __restrict__ gwh1,
    const float* __restrict__ gbi1, const float* __restrict__ gbh1,
    const float* __restrict__ brw, const float* __restrict__ fc1w)
{
    int i0 = blockIdx.x * blockDim.x + threadIdx.x;
    int st = gridDim.x * blockDim.x;
    for (int i = i0; i < 4 * 512; i += st) {
        int k = i >> 9, jg = i & 511, j = jg >> 2, g = jg & 3;
        g_wx0[i] = lwih0[(g * 128 + j) * 4 + k];
    }
    for (int i = i0; i < 128 * 512; i += st) {
        int k = i >> 9, jg = i & 511, j = jg >> 2, g = jg & 3;
        int row = g * 128 + j;
        g_wh0[i] = __float2half(lwhh0[row * 128 + k]);
        g_wi1[i] = __float2half(lwih1[row * 128 + k]);
        g_wh1[i] = __float2half(lwhh1[row * 128 + k]);
        g_wgi0[i] = __float2half((g < 3) ? gwi0[row * 128 + k] : 0.f);
        g_wgh0[i] = __float2half((g < 3) ? gwh0[row * 128 + k] : 0.f);
        g_wgi1[i] = __float2half((g < 3) ? gwi1[row * 128 + k] : 0.f);
        g_wgh1[i] = __float2half((g < 3) ? gwh1[row * 128 + k] : 0.f);
    }
    for (int i = i0; i < 512; i += st) {
        int j = i >> 2, g = i & 3;
        int row = g * 128 + j;
        g_b0[i] = lbih0[row] + lbhh0[row];
        g_b1[i] = lbih1[row] + lbhh1[row];
        g_bgi0[i] = (g < 3) ? gbi0[row] : 0.f;
        g_bgh0[i] = (g < 3) ? gbh0[row] : 0.f;
        g_bgi1[i] = (g < 3) ? gbi1[row] : 0.f;
        g_bgh1[i] = (g < 3) ? gbh1[row] : 0.f;
    }
    for (int i = i0; i < 128 * 128; i += st) {
        int k = i >> 7, j = i & 127;
        g_wbr[i] = brw[j * 128 + k];
    }
    for (int i = i0; i < 128 * 64; i += st) {
        int k = i / 64, c = i % 64;
        g_wfc1[i] = fc1w[c * 128 + k];
    }
}

__device__ __forceinline__ float sigm(float v) { return 1.f / (1.f + __expf(-v)); }

// acc[q][g] += sum_k A[r0+q][k] * half2float(W[k][j*4+g]); fp32 accumulate.
// Weight row per k = 8 bytes (4 halves) -> LDG.64, half the L1 wavefronts of fp32.
template<int NG>
__device__ __forceinline__ void mmh(const float* __restrict__ A,
                                    const __half* __restrict__ W,
                                    int r0, int j4, float (&acc)[4][NG])
{
#pragma unroll 4
    for (int k = 0; k < 128; k += 4) {
        float w[4][4];
#pragma unroll
        for (int kk = 0; kk < 4; kk++) {
            __half2 h[2];
            *(uint2*)h = *(const uint2*)(W + (size_t)(k + kk) * 512 + j4);
            float2 lo = __half22float2(h[0]);
            w[kk][0] = lo.x; w[kk][1] = lo.y;
            if (NG == 4) {
                float2 hi = __half22float2(h[1]);
                w[kk][2] = hi.x; w[kk][3] = hi.y;
            } else {
                w[kk][2] = __low2float(h[1]);
            }
        }
#pragma unroll
        for (int q = 0; q < 4; q++) {
            float4 a = *(const float4*)(A + (r0 + q) * H + k);
#pragma unroll
            for (int g = 0; g < NG; g++) {
                acc[q][g] = fmaf(a.x, w[0][g], acc[q][g]);
                acc[q][g] = fmaf(a.y, w[1][g], acc[q][g]);
                acc[q][g] = fmaf(a.z, w[2][g], acc[q][g]);
                acc[q][g] = fmaf(a.w, w[3][g], acc[q][g]);
            }
        }
    }
}

__global__ void __launch_bounds__(NTHR, 1) rnn_kernel(
    const float* __restrict__ x,
    const float* __restrict__ brb, const float* __restrict__ fc1b,
    const float* __restrict__ fc2w, const float* __restrict__ fc2b,
    float* __restrict__ out)
{
    extern __shared__ float sm[];
    float* xs  = sm;              // [16][256]
    float* h0b = xs + 4096;       // [2][16][128] ping-pong
    float* h1b = h0b + 4096;
    float* d0b = h1b + 4096;
    float* d1b = d0b + 4096;
    float* fcz = d1b + 4096;      // [16][64]

    const int tid = threadIdx.x;
    const int rg = tid >> 7;
    const int j  = tid & 127;
    const int j4 = j * 4;
    const int r0 = rg * 4;
    const int b0 = blockIdx.x * BT;

    for (int i = tid; i < BT * 256; i += NTHR) {
        int r = i >> 8, q = i & 255;
        xs[i] = x[(size_t)(b0 + r) * 256 + q];
    }
#pragma unroll
    for (int q = 0; q < 4; q++) {
        h0b[(r0 + q) * H + j] = 0.f;
        h1b[(r0 + q) * H + j] = 0.f;
    }
    float c0r[4] = {0.f, 0.f, 0.f, 0.f};
    float c1r[4] = {0.f, 0.f, 0.f, 0.f};
    __syncthreads();

    // ---------------- LSTM encoder ----------------
    for (int t = 0; t < S; t++) {
        const int p = t & 1, np = p ^ 1;
        const float* h0p = h0b + p * 2048;
        float*       h0n = h0b + np * 2048;
        const float* h1p = h1b + p * 2048;
        float*       h1n = h1b + np * 2048;

        // layer 0
        {
            float acc[4][4];
            float4 bb = *(const float4*)(g_b0 + j4);
#pragma unroll
            for (int q = 0; q < 4; q++) {
                acc[q][0] = bb.x; acc[q][1] = bb.y; acc[q][2] = bb.z; acc[q][3] = bb.w;
            }
            float4 w0 = *(const float4*)(g_wx0 + 0 * 512 + j4);
            float4 w1 = *(const float4*)(g_wx0 + 1 * 512 + j4);
            float4 w2 = *(const float4*)(g_wx0 + 2 * 512 + j4);
            float4 w3 = *(const float4*)(g_wx0 + 3 * 512 + j4);
#pragma unroll
            for (int q = 0; q < 4; q++) {
                float4 a = *(const float4*)(xs + (r0 + q) * 256 + t * 4);
                acc[q][0] = fmaf(a.x, w0.x, acc[q][0]); acc[q][1] = fmaf(a.x, w0.y, acc[q][1]);
                acc[q][2] = fmaf(a.x, w0.z, acc[q][2]); acc[q][3] = fmaf(a.x, w0.w, acc[q][3]);
                acc[q][0] = fmaf(a.y, w1.x, acc[q][0]); acc[q][1] = fmaf(a.y, w1.y, acc[q][1]);
                acc[q][2] = fmaf(a.y, w1.z, acc[q][2]); acc[q][3] = fmaf(a.y, w1.w, acc[q][3]);
                acc[q][0] = fmaf(a.z, w2.x, acc[q][0]); acc[q][1] = fmaf(a.z, w2.y, acc[q][1]);
                acc[q][2] = fmaf(a.z, w2.z, acc[q][2]); acc[q][3] = fmaf(a.z, w2.w, acc[q][3]);
                acc[q][0] = fmaf(a.w, w3.x, acc[q][0]); acc[q][1] = fmaf(a.w, w3.y, acc[q][1]);
                acc[q][2] = fmaf(a.w, w3.z, acc[q][2]); acc[q][3] = fmaf(a.w, w3.w, acc[q][3]);
            }
            mmh<4>(h0p, g_wh0, r0, j4, acc);
#pragma unroll
            for (int q = 0; q < 4; q++) {
                float cc = sigm(acc[q][1]) * c0r[q] + sigm(acc[q][0]) * tanhf(acc[q][2]);
                c0r[q] = cc;
                h0n[(r0 + q) * H + j] = sigm(acc[q][3]) * tanhf(cc);
            }
        }
        __syncthreads();

        // layer 1
        {
            float acc[4][4];
            float4 bb = *(const float4*)(g_b1 + j4);
#pragma unroll
            for (int q = 0; q < 4; q++) {
                acc[q][0] = bb.x; acc[q][1] = bb.y; acc[q][2] = bb.z; acc[q][3] = bb.w;
            }
            mmh<4>(h0n, g_wi1, r0, j4, acc);
            mmh<4>(h1p, g_wh1, r0, j4, acc);
#pragma unroll
            for (int q = 0; q < 4; q++) {
                float cc = sigm(acc[q][1]) * c1r[q] + sigm(acc[q][0]) * tanhf(acc[q][2]);
                c1r[q] = cc;
                h1n[(r0 + q) * H + j] = sigm(acc[q][3]) * tanhf(cc);
            }
        }
        __syncthreads();
    }
    const float* h0f = h0b;   // final states in buffer 0 after t=63
    const float* h1f = h1b;

    // ---------------- bridge ----------------
    {
        float a0[4], a1[4];
        float bv = brb[j];
#pragma unroll
        for (int q = 0; q < 4; q++) { a0[q] = bv; a1[q] = bv; }
#pragma unroll 4
        for (int k = 0; k < 128; k += 4) {
            float w0 = g_wbr[(k + 0) * 128 + j];
            float w1 = g_wbr[(k + 1) * 128 + j];
            float w2 = g_wbr[(k + 2) * 128 + j];
            float w3 = g_wbr[(k + 3) * 128 + j];
#pragma unroll
            for (int q = 0; q < 4; q++) {
                float4 u = *(const float4*)(h0f + (r0 + q) * H + k);
                float4 v = *(const float4*)(h1f + (r0 + q) * H + k);
                a0[q] = fmaf(u.x, w0, a0[q]); a0[q] = fmaf(u.y, w1, a0[q]);
                a0[q] = fmaf(u.z, w2, a0[q]); a0[q] = fmaf(u.w, w3, a0[q]);
                a1[q] = fmaf(v.x, w0, a1[q]); a1[q] = fmaf(v.y, w1, a1[q]);
                a1[q] = fmaf(v.z, w2, a1[q]); a1[q] = fmaf(v.w, w3, a1[q]);
            }
        }
#pragma unroll
        for (int q = 0; q < 4; q++) {
            d0b[(r0 + q) * H + j] = tanhf(a0[q]);
            d1b[(r0 + q) * H + j] = tanhf(a1[q]);
        }
    }
    __syncthreads();

    // ---------------- autoregressive GRU decode + head ----------------
    for (int t = 0; t < PRED; t++) {
        const int pg = t & 1, npg = pg ^ 1;
        const float* d0p = d0b + pg * 2048;
        float*       d0n = d0b + npg * 2048;
        const float* d1p = d1b + pg * 2048;
        float*       d1n = d1b + npg * 2048;
        const float* A1 = (t == 0) ? h1f : d1p;

        // GRU layer 0
        {
            float ai[4][3], ah[4][3];
            float4 bi = *(const float4*)(g_bgi0 + j4);
            float4 bh = *(const float4*)(g_bgh0 + j4);
#pragma unroll
            for (int q = 0; q < 4; q++) {
                ai[q][0] = bi.x; ai[q][1] = bi.y; ai[q][2] = bi.z;
                ah[q][0] = bh.x; ah[q][1] = bh.y; ah[q][2] = bh.z;
            }
            mmh<3>(A1, g_wgi0, r0, j4, ai);
            mmh<3>(d0p, g_wgh0, r0, j4, ah);
#pragma unroll
            for (int q = 0; q < 4; q++) {
                float hold = d0p[(r0 + q) * H + j];
                float rr = sigm(ai[q][0] + ah[q][0]);
                float zz = sigm(ai[q][1] + ah[q][1]);
                float nn = tanhf(ai[q][2] + rr * ah[q][2]);
                d0n[(r0 + q) * H + j] = (1.f - zz) * nn + zz * hold;
            }
        }
        __syncthreads();

        // GRU layer 1
        {
            float ai[4][3], ah[4][3];
            float4 bi = *(const float4*)(g_bgi1 + j4);
            float4 bh = *(const float4*)(g_bgh1 + j4);
#pragma unroll
            for (int q = 0; q < 4; q++) {
                ai[q][0] = bi.x; ai[q][1] = bi.y; ai[q][2] = bi.z;
                ah[q][0] = bh.x; ah[q][1] = bh.y; ah[q][2] = bh.z;
            }
            mmh<3>(d0n, g_wgi1, r0, j4, ai);
            mmh<3>(d1p, g_wgh1, r0, j4, ah);
#pragma unroll
            for (int q = 0; q < 4; q++) {
                float hold = d1p[(r0 + q) * H + j];
                float rr = sigm(ai[q][0] + ah[q][0]);
                float zz = sigm(ai[q][1] + ah[q][1]);
                float nn = tanhf(ai[q][2] + rr * ah[q][2]);
                d1n[(r0 + q) * H + j] = (1.f - zz) * nn + zz * hold;
            }
        }
        __syncthreads();

        // fc1 (relu): 1024 outputs, 2 per thread
#pragma unroll
        for (int half = 0; half < 2; half++) {
            int o = tid + half * NTHR;
            int r = o >> 6, c = o & 63;
            float acc = fc1b[c];
#pragma unroll 4
            for (int k = 0; k < 128; k += 4) {
                float4 hv = *(const float4*)(d1n + r * H + k);
                acc = fmaf(hv.x, g_wfc1[(k + 0) * 64 + c], acc);
                acc = fmaf(hv.y, g_wfc1[(k + 1) * 64 + c], acc);
                acc = fmaf(hv.z, g_wfc1[(k + 2) * 64 + c], acc);
                acc = fmaf(hv.w, g_wfc1[(k + 3) * 64 + c], acc);
            }
            fcz[r * 64 + c] = fmaxf(acc, 0.f);
        }
        __syncthreads();

        // fc2: 16 rows x 2 cols
        if (tid < 32) {
            int r = tid >> 1, cc = tid & 1;
            float s = fc2b[cc];
#pragma unroll
            for (int k = 0; k < 64; k++)
                s = fmaf(fcz[r * 64 + k], fc2w[cc * 64 + k], s);
            out[(size_t)(b0 + r) * PRED * 2 + t * 2 + cc] = s;
        }
        __syncthreads();
    }
}

extern "C" void kernel_launch(void* const* d_in, const int* in_sizes, int n_in,
                              void* d_out, int out_size)
{
    const float* p[24];
    int np = 0;
    for (int i = 0; i < n_in && np < 24; i++) {
        if (in_sizes[i] == 1) continue;
        p[np++] = (const float*)d_in[i];
    }
    const float* x = p[0];
    const float *lwih0 = p[1], *lwhh0 = p[2], *lbih0 = p[3], *lbhh0 = p[4];
    const float *lwih1 = p[5], *lwhh1 = p[6], *lbih1 = p[7], *lbhh1 = p[8];
    const float *gwi0 = p[9], *gwh0 = p[10], *gbi0 = p[11], *gbh0 = p[12];
    const float *gwi1 = p[13], *gwh1 = p[14], *gbi1 = p[15], *gbh1 = p[16];
    const float *brw = p[17], *brb = p[18];
    const float *fc1w = p[19], *fc1b = p[20];
    const float *fc2w = p[21], *fc2b = p[22];

    prep_kernel<<<256, 256>>>(lwih0, lwhh0, lbih0, lbhh0, lwih1, lwhh1, lbih1, lbhh1,
                              gwi0, gwh0, gbi0, gbh0, gwi1, gwh1, gbi1, gbh1,
                              brw, fc1w);

    const int smem = (4096 * 5 + 1024) * (int)sizeof(float);   // 86016 B
    cudaFuncSetAttribute(rnn_kernel, cudaFuncAttributeMaxDynamicSharedMemorySize, smem);
    rnn_kernel<<<NBLK, NTHR, smem>>>(x, brb, fc1b, fc2w, fc2b, (float*)d_out);
}

// round 7
// speedup vs baseline: 3.8223x; 3.3968x over previous
#include <cuda_runtime.h>
#include <cuda_fp16.h>
#include <math.h>

#define H 128
#define S 64
#define PRED 50
#define BT 16
#define NBLK 128
#define NTHR 512

// ---------------- fragment-ordered weights: [ntile][kstep][lane][4 halves] ----------------
// B-fragment for mma.m16n8k16 (col): lane=gid*4+tig holds
//   {W[k0+2t][n], W[k0+2t+1][n], W[k0+2t+8][n], W[k0+2t+9][n]} with n = ntile*8+gid.
__device__ __align__(16) __half g_wf_l0[64 * 9 * 128];    // LSTM L0: K=144 (128 h + 4 x + pad), 512 cols
__device__ __align__(16) __half g_wf_l1[64 * 16 * 128];   // LSTM L1: K=256 (wih1|whh1), 512 cols
__device__ __align__(16) __half g_wf_gi0[48 * 8 * 128];   // GRU: 384 cols, K=128
__device__ __align__(16) __half g_wf_gh0[48 * 8 * 128];
__device__ __align__(16) __half g_wf_gi1[48 * 8 * 128];
__device__ __align__(16) __half g_wf_gh1[48 * 8 * 128];
__device__ __align__(16) __half g_wf_br[16 * 8 * 128];    // bridge: 128 cols, K=128
__device__ __align__(16) float  g_b0[512];                // natural order n = g*128+j
__device__ __align__(16) float  g_b1[512];
__device__ __align__(16) float  g_bgi0[384];
__device__ __align__(16) float  g_bgh0[384];
__device__ __align__(16) float  g_bgi1[384];
__device__ __align__(16) float  g_bgh1[384];
__device__ __align__(16) float  g_wfc1[128 * 64];         // [k][c] fp32

__global__ void prep_kernel(
    const float* __restrict__ lwih0, const float* __restrict__ lwhh0,
    const float* __restrict__ lbih0, const float* __restrict__ lbhh0,
    const float* __restrict__ lwih1, const float* __restrict__ lwhh1,
    const float* __restrict__ lbih1, const float* __restrict__ lbhh1,
    const float* __restrict__ gwi0, const float* __restrict__ gwh0,
    const float* __restrict__ gbi0, const float* __restrict__ gbh0,
    const float* __restrict__ gwi1, const float* __restrict__ gwh1,
    const float* __restrict__ gbi1, const float* __restrict__ gbh1,
    const float* __restrict__ brw, const float* __restrict__ fc1w)
{
    int i0 = blockIdx.x * blockDim.x + threadIdx.x;
    int st = gridDim.x * blockDim.x;

    // decode i -> (nt, s, lane, e) for given KS; then n,k
#define FRAG_DECODE(i, KS)                                  \
    int e = (i) & 3;                                        \
    int lane = ((i) >> 2) & 31;                             \
    int q2 = (i) >> 7;                                      \
    int s = q2 % (KS);                                      \
    int nt = q2 / (KS);                                     \
    int n = nt * 8 + (lane >> 2);                           \
    int k = s * 16 + (lane & 3) * 2 + (e & 1) + (e >> 1) * 8;

    for (int i = i0; i < 64 * 9 * 128; i += st) {
        FRAG_DECODE(i, 9);
        float v = 0.f;
        if (k < 128)      v = lwhh0[n * 128 + k];
        else if (k < 132) v = lwih0[n * 4 + (k - 128)];
        g_wf_l0[i] = __float2half(v);
    }
    for (int i = i0; i < 64 * 16 * 128; i += st) {
        FRAG_DECODE(i, 16);
        float v = (k < 128) ? lwih1[n * 128 + k] : lwhh1[n * 128 + (k - 128)];
        g_wf_l1[i] = __float2half(v);
    }
    for (int i = i0; i < 48 * 8 * 128; i += st) {
        FRAG_DECODE(i, 8);
        g_wf_gi0[i] = __float2half(gwi0[n * 128 + k]);
        g_wf_gh0[i] = __float2half(gwh0[n * 128 + k]);
        g_wf_gi1[i] = __float2half(gwi1[n * 128 + k]);
        g_wf_gh1[i] = __float2half(gwh1[n * 128 + k]);
    }
    for (int i = i0; i < 16 * 8 * 128; i += st) {
        FRAG_DECODE(i, 8);
        g_wf_br[i] = __float2half(brw[n * 128 + k]);
    }
#undef FRAG_DECODE
    for (int i = i0; i < 512; i += st) {
        g_b0[i] = lbih0[i] + lbhh0[i];
        g_b1[i] = lbih1[i] + lbhh1[i];
    }
    for (int i = i0; i < 384; i += st) {
        g_bgi0[i] = gbi0[i]; g_bgh0[i] = gbh0[i];
        g_bgi1[i] = gbi1[i]; g_bgh1[i] = gbh1[i];
    }
    for (int i = i0; i < 128 * 64; i += st) {
        int k = i / 64, c = i % 64;
        g_wfc1[i] = fc1w[c * 128 + k];
    }
}

__device__ __forceinline__ float sigm(float v) { return 1.f / (1.f + __expf(-v)); }

__device__ __forceinline__ unsigned smem_u32(const void* p) {
    return (unsigned)__cvta_generic_to_shared(p);
}
__device__ __forceinline__ void ldsm_x4(unsigned addr, unsigned& r0, unsigned& r1,
                                        unsigned& r2, unsigned& r3) {
    asm volatile("ldmatrix.sync.aligned.m8n8.x4.shared.b16 {%0,%1,%2,%3}, [%4];\n"
                 : "=r"(r0), "=r"(r1), "=r"(r2), "=r"(r3) : "r"(addr));
}
__device__ __forceinline__ void hmma(float* c, unsigned a0, unsigned a1, unsigned a2,
                                     unsigned a3, unsigned b0, unsigned b1) {
    asm volatile("mma.sync.aligned.m16n8k16.row.col.f32.f16.f16.f32 "
                 "{%0,%1,%2,%3}, {%4,%5,%6,%7}, {%8,%9}, {%0,%1,%2,%3};\n"
                 : "+f"(c[0]), "+f"(c[1]), "+f"(c[2]), "+f"(c[3])
                 : "r"(a0), "r"(a1), "r"(a2), "r"(a3), "r"(b0), "r"(b1));
}

// Warp GEMM: C[16 x NT*8] (cols ntile0*8..) = A[16 x KS*16] @ W + 0, C -> smem fp32.
// A: smem fp16, row stride astr halves (multiple of 8, odd in 16B units for no LDSM conflicts).
template<int NT, int KS>
__device__ __forceinline__ void hgemm(const __half* A, int astr,
                                      const __half* __restrict__ WF,
                                      int ntile0, float* outp, int ostr)
{
    const int lane = threadIdx.x & 31;
    unsigned abase = smem_u32(A) + (unsigned)(((lane & 15) * astr + ((lane >> 4) << 3)) * 2);
    float c[NT][4];
#pragma unroll
    for (int i = 0; i < NT; i++) { c[i][0] = c[i][1] = c[i][2] = c[i][3] = 0.f; }
#pragma unroll
    for (int s = 0; s < KS; s++) {
        unsigned a0, a1, a2, a3;
        ldsm_x4(abase + s * 32, a0, a1, a2, a3);
#pragma unroll
        for (int i = 0; i < NT; i++) {
            uint2 b = *(const uint2*)(WF + (((size_t)(ntile0 + i) * KS + s) * 32 + lane) * 4);
            hmma(c[i], a0, a1, a2, a3, b.x, b.y);
        }
    }
    const int gid = lane >> 2, tig = lane & 3;
#pragma unroll
    for (int i = 0; i < NT; i++) {
        int n = (ntile0 + i) * 8 + tig * 2;
        *(float2*)(outp + gid * ostr + n) = make_float2(c[i][0], c[i][1]);
        *(float2*)(outp + (gid + 8) * ostr + n) = make_float2(c[i][2], c[i][3]);
    }
}

// smem strides (halves); all multiples of 8, odd multiples of 8 -> LDSM conflict-free
#define STR_A  152   // bufA: [16][152], cols 0-127 h0, 128-131 x, 132-143 zero-pad (read), rest pad
#define STR_B  264   // bufB: [16][264], cols 0-127 h0_new, 128-255 h1
#define STR_D  136   // d buffers: [16][136], cols 0-127
#define GST    520   // LSTM/bridge gate buffer stride (floats)
#define GSTG   392   // GRU gate buffer stride (floats)

__global__ void __launch_bounds__(NTHR, 1) rnn_kernel(
    const float* __restrict__ x,
    const float* __restrict__ brb, const float* __restrict__ fc1b,
    const float* __restrict__ fc2w, const float* __restrict__ fc2b,
    float* __restrict__ out)
{
    extern __shared__ char smraw[];
    __half* xs   = (__half*)smraw;                       // [16][256]
    __half* bufA = (__half*)(smraw + 8192);              // [2][16][152]
    __half* bufB = (__half*)(smraw + 8192 + 9728);       // [2][16][264]
    __half* d0b  = (__half*)(smraw + 8192 + 9728 + 16896);          // [2][16][136]
    __half* d1b  = (__half*)(smraw + 8192 + 9728 + 16896 + 8704);   // [2][16][136]
    float*  gbuf = (float*)(smraw + 8192 + 9728 + 16896 + 8704 + 8704);  // 12544 floats
    float*  fcz  = (float*)(smraw + 8192 + 9728 + 16896 + 8704 + 8704 + 50176); // [16][64]

    const int tid = threadIdx.x;
    const int wid = tid >> 5;
    const int b0 = blockIdx.x * BT;

    // init: x tile (fp16), zero bufA/bufB (both buffers), x_0 into bufA[0]
    for (int i = tid; i < BT * 256; i += NTHR) {
        int r = i >> 8, q = i & 255;
        xs[i] = __float2half(x[(size_t)(b0 + r) * 256 + q]);
    }
    for (int i = tid; i < 2 * 16 * STR_A; i += NTHR) bufA[i] = __float2half(0.f);
    for (int i = tid; i < 2 * 16 * STR_B; i += NTHR) bufB[i] = __float2half(0.f);
    if (tid < 64) {
        int r = tid >> 2, k = tid & 3;
        bufA[r * STR_A + 128 + k] = __float2half(x[(size_t)(b0 + r) * 256 + k]);
    }
    float c0r[4] = {0.f, 0.f, 0.f, 0.f};
    float c1r[4] = {0.f, 0.f, 0.f, 0.f};
    __syncthreads();

    // ---------------- LSTM encoder ----------------
    for (int t = 0; t < S; t++) {
        const int p = t & 1, np = p ^ 1;
        __half* A0 = bufA + p * 16 * STR_A;
        __half* A0n = bufA + np * 16 * STR_A;
        __half* Bp = bufB + p * 16 * STR_B;
        __half* Bn = bufB + np * 16 * STR_B;

        // GEMM L0: gates[16][512] = A0[16][144] @ WF_l0  (x folded in K)
        hgemm<4, 9>(A0, STR_A, g_wf_l0, wid * 4, gbuf, GST);
        __syncthreads();

        // combine L0 -> h0_new (fp16) into bufA[np][0..127] and bufB[p][0..127]
#pragma unroll
        for (int it = 0; it < 4; it++) {
            int idx = tid + it * NTHR;
            int r = idx >> 7, j = idx & 127;
            const float* gr = gbuf + r * GST;
            float ii = gr[j]           + g_b0[j];
            float ff = gr[128 + j]     + g_b0[128 + j];
            float gg = gr[256 + j]     + g_b0[256 + j];
            float oo = gr[384 + j]     + g_b0[384 + j];
            float cc = sigm(ff) * c0r[it] + sigm(ii) * tanhf(gg);
            c0r[it] = cc;
            __half hh = __float2half(sigm(oo) * tanhf(cc));
            A0n[r * STR_A + j] = hh;
            Bp[r * STR_B + j] = hh;
        }
        __syncthreads();

        // GEMM L1: gates = [h0_new | h1_prev][16][256] @ WF_l1
        hgemm<4, 16>(Bp, STR_B, g_wf_l1, wid * 4, gbuf, GST);
        __syncthreads();

        // combine L1 -> h1_new into bufB[np][128..255]; prefetch x_{t+1} into bufA[np]
#pragma unroll
        for (int it = 0; it < 4; it++) {
            int idx = tid + it * NTHR;
            int r = idx >> 7, j = idx & 127;
            const float* gr = gbuf + r * GST;
            float ii = gr[j]           + g_b1[j];
            float ff = gr[128 + j]     + g_b1[128 + j];
            float gg = gr[256 + j]     + g_b1[256 + j];
            float oo = gr[384 + j]     + g_b1[384 + j];
            float cc = sigm(ff) * c1r[it] + sigm(ii) * tanhf(gg);
            c1r[it] = cc;
            Bn[r * STR_B + 128 + j] = __float2half(sigm(oo) * tanhf(cc));
        }
        if (t < S - 1 && tid < 64) {
            int r = tid >> 2, k = tid & 3;
            A0n[r * STR_A + 128 + k] = xs[r * 256 + (t + 1) * 4 + k];
        }
        __syncthreads();
    }
    // finals: h0f = bufA[0][0..127], h1f = bufB[0][128..255]
    __half* h0f = bufA;
    __half* h1f = bufB + 128;

    // ---------------- bridge: hg = tanh(h @ br^T + b) for h0f, h1f ----------------
    if (wid < 8) hgemm<2, 8>(h0f, STR_A, g_wf_br, wid * 2, gbuf, GST);
    else         hgemm<2, 8>(h1f, STR_B, g_wf_br, (wid - 8) * 2, gbuf + 128, GST);
    __syncthreads();
#pragma unroll
    for (int it = 0; it < 4; it++) {
        int idx = tid + it * NTHR;
        int r = idx >> 7, j = idx & 127;
        float bv = brb[j];
        d0b[r * STR_D + j] = __float2half(tanhf(gbuf[r * GST + j] + bv));
        d1b[r * STR_D + j] = __float2half(tanhf(gbuf[r * GST + 128 + j] + bv));
    }
    __syncthreads();

    float* giB = gbuf;                 // [16][392]
    float* ghB = gbuf + 16 * GSTG;     // [16][392]

    // ---------------- autoregressive GRU decode + head ----------------
    for (int t = 0; t < PRED; t++) {
        const int pg = t & 1, npg = pg ^ 1;
        __half* d0p = d0b + pg * 16 * STR_D;
        __half* d0n = d0b + npg * 16 * STR_D;
        __half* d1p = d1b + pg * 16 * STR_D;
        __half* d1n = d1b + npg * 16 * STR_D;
        const __half* A1 = (t == 0) ? h1f : d1p;
        const int a1str = (t == 0) ? STR_B : STR_D;

        // GRU layer 0: gi = A1 @ Wgi0, gh = d0p @ Wgh0
        hgemm<3, 8>(A1, a1str, g_wf_gi0, wid * 3, giB, GSTG);
        hgemm<3, 8>(d0p, STR_D, g_wf_gh0, wid * 3, ghB, GSTG);
        __syncthreads();
#pragma unroll
        for (int it = 0; it < 4; it++) {
            int idx = tid + it * NTHR;
            int r = idx >> 7, j = idx & 127;
            const float* gi = giB + r * GSTG;
            const float* gh = ghB + r * GSTG;
            float rr = sigm(gi[j] + g_bgi0[j] + gh[j] + g_bgh0[j]);
            float zz = sigm(gi[128 + j] + g_bgi0[128 + j] + gh[128 + j] + g_bgh0[128 + j]);
            float nn = tanhf(gi[256 + j] + g_bgi0[256 + j] + rr * (gh[256 + j] + g_bgh0[256 + j]));
            float hold = __half2float(d0p[r * STR_D + j]);
            d0n[r * STR_D + j] = __float2half((1.f - zz) * nn + zz * hold);
        }
        __syncthreads();

        // GRU layer 1
        hgemm<3, 8>(d0n, STR_D, g_wf_gi1, wid * 3, giB, GSTG);
        hgemm<3, 8>(d1p, STR_D, g_wf_gh1, wid * 3, ghB, GSTG);
        __syncthreads();
#pragma unroll
        for (int it = 0; it < 4; it++) {
            int idx = tid + it * NTHR;
            int r = idx >> 7, j = idx & 127;
            const float* gi = giB + r * GSTG;
            const float* gh = ghB + r * GSTG;
            float rr = sigm(gi[j] + g_bgi1[j] + gh[j] + g_bgh1[j]);
            float zz = sigm(gi[128 + j] + g_bgi1[128 + j] + gh[128 + j] + g_bgh1[128 + j]);
            float nn = tanhf(gi[256 + j] + g_bgi1[256 + j] + rr * (gh[256 + j] + g_bgh1[256 + j]));
            float hold = __half2float(d1p[r * STR_D + j]);
            d1n[r * STR_D + j] = __float2half((1.f - zz) * nn + zz * hold);
        }
        __syncthreads();

        // fc1 (relu): 1024 outputs, 2 per thread, d1n fp16 input
#pragma unroll
        for (int half = 0; half < 2; half++) {
            int o = tid + half * NTHR;
            int r = o >> 6, c = o & 63;
            float acc = fc1b[c];
#pragma unroll 4
            for (int k = 0; k < 128; k += 2) {
                __half2 hv = *(const __half2*)(d1n + r * STR_D + k);
                float2 fv = __half22float2(hv);
                acc = fmaf(fv.x, g_wfc1[(k + 0) * 64 + c], acc);
                acc = fmaf(fv.y, g_wfc1[(k + 1) * 64 + c], acc);
            }
            fcz[r * 64 + c] = fmaxf(acc, 0.f);
        }
        __syncthreads();

        // fc2: 16 rows x 2 cols
        if (tid < 32) {
            int r = tid >> 1, cc = tid & 1;
            float s = fc2b[cc];
#pragma unroll
            for (int k = 0; k < 64; k++)
                s = fmaf(fcz[r * 64 + k], fc2w[cc * 64 + k], s);
            out[(size_t)(b0 + r) * PRED * 2 + t * 2 + cc] = s;
        }
        __syncthreads();
    }
}

extern "C" void kernel_launch(void* const* d_in, const int* in_sizes, int n_in,
                              void* d_out, int out_size)
{
    const float* p[24];
    int np = 0;
    for (int i = 0; i < n_in && np < 24; i++) {
        if (in_sizes[i] == 1) continue;
        p[np++] = (const float*)d_in[i];
    }
    const float* x = p[0];
    const float *lwih0 = p[1], *lwhh0 = p[2], *lbih0 = p[3], *lbhh0 = p[4];
    const float *lwih1 = p[5], *lwhh1 = p[6], *lbih1 = p[7], *lbhh1 = p[8];
    const float *gwi0 = p[9], *gwh0 = p[10], *gbi0 = p[11], *gbh0 = p[12];
    const float *gwi1 = p[13], *gwh1 = p[14], *gbi1 = p[15], *gbh1 = p[16];
    const float *brw = p[17], *brb = p[18];
    const float *fc1w = p[19], *fc1b = p[20];
    const float *fc2w = p[21], *fc2b = p[22];

    prep_kernel<<<512, 256>>>(lwih0, lwhh0, lbih0, lbhh0, lwih1, lwhh1, lbih1, lbhh1,
                              gwi0, gwh0, gbi0, gbh0, gwi1, gwh1, gbi1, gbh1,
                              brw, fc1w);

    const int smem = 8192 + 9728 + 16896 + 8704 + 8704 + 50176 + 4096;  // 106496 B
    cudaFuncSetAttribute(rnn_kernel, cudaFuncAttributeMaxDynamicSharedMemorySize, smem);
    rnn_kernel<<<NBLK, NTHR, smem>>>(x, brb, fc1b, fc2w, fc2b, (float*)d_out);
}